// round 11
// baseline (speedup 1.0000x reference)
#include <cuda_runtime.h>
#include <cuda_bf16.h>
#include <math.h>
#include <stdint.h>

#define NROWS 32768
#define D 1024
#define NCLS 10
#define NBLK 128           /* NROWS / 256 */
#define PADN 33408         /* 32768 + 10*64 : padded permuted-row capacity */

// ---------------- static device scratch (no runtime allocation) ----------------
__device__ int    d_counts[NCLS];
__device__ int    d_poff[NCLS];        // padded class starts
__device__ int    d_plen[NCLS];        // padded class lengths (mult of 64)
__device__ int    d_blockCnt[NBLK][NCLS];
__device__ int    d_permPad[PADN];     // padded permuted index -> original row (-1 = hole)
__device__ float  d_scales[32];
__device__ float  d_G[20][D * D];      // 0..9: GZ_j, 10..19: GZb_j
__device__ float  d_A[32][D * D];      // matrices to factorize
__device__ double d_logdet[32];
__device__ __nv_bfloat16 d_Zhi[2][(size_t)D * PADN];  // transposed, permuted, padded
__device__ __nv_bfloat16 d_Zlo[2][(size_t)D * PADN];

// ---------------- PTX helpers (base ISA only: ldmatrix / mma.sync / cp.async) ----------------
__device__ __forceinline__ uint32_t smem_u32(const void* p) {
    uint32_t a;
    asm("{ .reg .u64 t; cvta.to.shared.u64 t, %1; cvt.u32.u64 %0, t; }" : "=r"(a) : "l"(p));
    return a;
}
__device__ __forceinline__ void ldsm4(uint32_t* r, uint32_t addr) {
    asm volatile("ldmatrix.sync.aligned.m8n8.x4.shared.b16 {%0,%1,%2,%3}, [%4];"
                 : "=r"(r[0]), "=r"(r[1]), "=r"(r[2]), "=r"(r[3]) : "r"(addr));
}
__device__ __forceinline__ void mma_bf16(float* d, const uint32_t* a, const uint32_t* b) {
    asm volatile(
        "mma.sync.aligned.m16n8k16.row.col.f32.bf16.bf16.f32 "
        "{%0,%1,%2,%3}, {%4,%5,%6,%7}, {%8,%9}, {%0,%1,%2,%3};"
        : "+f"(d[0]), "+f"(d[1]), "+f"(d[2]), "+f"(d[3])
        : "r"(a[0]), "r"(a[1]), "r"(a[2]), "r"(a[3]), "r"(b[0]), "r"(b[1]));
}
__device__ __forceinline__ void cp16(uint32_t dst, const void* src) {
    asm volatile("cp.async.cg.shared.global [%0], [%1], 16;" :: "r"(dst), "l"(src));
}

// ---------------- label histogram / padded stable permutation ----------------
__global__ void init_permpad() {
    int i = blockIdx.x * 256 + threadIdx.x;
    if (i < PADN) d_permPad[i] = -1;
}

__global__ void count_kernel(const int* __restrict__ lab) {
    __shared__ int cnt[NCLS];
    int tid = threadIdx.x;
    if (tid < NCLS) cnt[tid] = 0;
    __syncthreads();
    atomicAdd(&cnt[lab[blockIdx.x * 256 + tid]], 1);
    __syncthreads();
    if (tid < NCLS) d_blockCnt[blockIdx.x][tid] = cnt[tid];
}

__global__ void scan_kernel() {
    if (threadIdx.x != 0) return;
    int poff = 0;
    for (int c = 0; c < NCLS; c++) {
        d_poff[c] = poff;
        int run = poff;
        for (int b = 0; b < NBLK; b++) {
            int v = d_blockCnt[b][c];
            d_blockCnt[b][c] = run;   // padded-domain start for block b, class c
            run += v;
        }
        int cnt = run - poff;
        d_counts[c] = cnt;
        d_plen[c] = (cnt + 63) & ~63;
        poff += d_plen[c];
    }
    d_scales[0] = d_scales[1] = (float)((double)D / ((double)NROWS * 0.5));
    for (int c = 0; c < NCLS; c++) {
        double cj = (double)d_counts[c];
        double tr = cj + 1e-8;
        float s = (float)((double)D / (tr * 0.5));
        d_scales[2 + c]  = s;
        d_scales[12 + c] = s;
        d_scales[22 + c] = (float)((double)D / (2.0 * cj * 0.5));
    }
}

__global__ void scatter_kernel(const int* __restrict__ lab) {
    __shared__ int s_lab[256];
    int tid = threadIdx.x;
    int gid = blockIdx.x * 256 + tid;
    int c = lab[gid];
    s_lab[tid] = c;
    __syncthreads();
    int rank = 0;
    for (int j = 0; j < tid; j++) rank += (s_lab[j] == c);
    d_permPad[d_blockCnt[blockIdx.x][c] + rank] = gid;
}

// ---------------- transpose + fp32 -> bf16(hi,lo) convert ----------------
__global__ __launch_bounds__(256) void convert_kernel(const float* __restrict__ Z0,
                                                      const float* __restrict__ Z1) {
    const float* __restrict__ Z = blockIdx.z ? Z1 : Z0;
    __nv_bfloat16* __restrict__ Th = d_Zhi[blockIdx.z];
    __nv_bfloat16* __restrict__ Tl = d_Zlo[blockIdx.z];
    int i0 = blockIdx.x * 32, m0 = blockIdx.y * 32;
    int tx = threadIdx.x & 31, ty = threadIdx.x >> 5;
    __shared__ float s[32][33];
    __shared__ int rp[32];
    if (threadIdx.x < 32) rp[threadIdx.x] = d_permPad[i0 + threadIdx.x];
    __syncthreads();
#pragma unroll
    for (int q = 0; q < 4; q++) {
        int il = ty + q * 8;
        int r = rp[il];
        s[il][tx] = (r >= 0) ? Z[(size_t)r * D + m0 + tx] : 0.0f;
    }
    __syncthreads();
#pragma unroll
    for (int q = 0; q < 4; q++) {
        int ml = ty + q * 8;
        float x = s[tx][ml];
        __nv_bfloat16 h = __float2bfloat16(x);
        __nv_bfloat16 l = __float2bfloat16(x - __bfloat162float(h));
        size_t o = (size_t)(m0 + ml) * PADN + i0 + tx;
        Th[o] = h;
        Tl[o] = l;
    }
}

// ---------------- per-class Gram via mma.sync bf16-split (3 MMAs) ----------------
// Block: 256 thr (8 warps, 4x2), tile 128x128, K-chunks of 32, cp.async 2-stage.
// smem parts per buffer (stride 80B/row): 0=Ahi 1=Alo 2=Bhi 3=Blo, 10240B each.
#define SOFF(buf, part) ((buf) * 40960 + (part) * 10240)
#define GRAM_SMEM (2 * 40960)

__device__ __forceinline__ void prefetch_chunk(const __nv_bfloat16* __restrict__ Zh,
                                               const __nv_bfloat16* __restrict__ Zl,
                                               uint32_t sb, int buf, int colA, int colB,
                                               int kb, bool diag, int tid) {
    int total = diag ? 1024 : 2048;
    for (int c = tid; c < total; c += 256) {
        int mat = c >> 9;            // 0=Ahi 1=Alo 2=Bhi 3=Blo
        int cc = c & 511;
        int m = cc >> 2, q = cc & 3;
        int col = (mat < 2) ? colA : colB;
        const __nv_bfloat16* base = (mat & 1) ? Zl : Zh;
        const __nv_bfloat16* src = base + (size_t)(col + m) * PADN + kb + q * 8;
        uint32_t dst = sb + SOFF(buf, mat) + m * 80 + q * 16;
        cp16(dst, src);
    }
    asm volatile("cp.async.commit_group;" ::: "memory");
}

__global__ __launch_bounds__(256, 1) void gram_mma() {
    extern __shared__ char smem[];
    uint32_t sb = smem_u32(smem);
    int tid = threadIdx.x;
    int wid = tid >> 5, lane = tid & 31;
    int a = 0, b = blockIdx.x;
    while (b >= 8 - a) { b -= 8 - a; a++; }
    b += a;
    int j = blockIdx.y, z = blockIdx.z;
    bool diag = (a == b);
    float* __restrict__ G = d_G[z * 10 + j];
    const __nv_bfloat16* __restrict__ Zh = d_Zhi[z];
    const __nv_bfloat16* __restrict__ Zl = d_Zlo[z];
    int off = d_poff[j];
    int nChunks = d_plen[j] >> 5;
    int colA = a * 128, colB = b * 128;

    if (nChunks == 0) {   // empty class: zero tile (+ mirror)
        if (tid < 128) {
            float4 z4 = make_float4(0.f, 0.f, 0.f, 0.f);
            for (int c = 0; c < 128; c += 4)
                *(float4*)&G[(size_t)(colA + tid) * D + colB + c] = z4;
            if (!diag)
                for (int c = 0; c < 128; c++)
                    G[(size_t)(colB + c) * D + colA + tid] = 0.f;
        }
        return;
    }

    int wm = wid & 3, wn = wid >> 2;          // warp tile: rows wm*32, cols wn*64
    int sub = lane & 7, idx = lane >> 3;
    int i0 = idx & 1, i1 = idx >> 1;
    // ldmatrix lane-address components
    int arow = wm * 32 + sub + i0 * 8;        // + mt*16
    int abyt = i1 * 16;                       // + kk*32
    int brow = wn * 64 + sub + i1 * 8;        // + np*16
    int bbyt = i0 * 16;                       // + kk*32

    float acc[2][8][4];
#pragma unroll
    for (int mt = 0; mt < 2; mt++)
#pragma unroll
        for (int nt = 0; nt < 8; nt++)
#pragma unroll
            for (int q = 0; q < 4; q++) acc[mt][nt][q] = 0.f;

    prefetch_chunk(Zh, Zl, sb, 0, colA, colB, off, diag, tid);
    if (nChunks > 1)
        prefetch_chunk(Zh, Zl, sb, 1, colA, colB, off + 32, diag, tid);

    for (int ch = 0; ch < nChunks; ch++) {
        if (ch + 2 <= nChunks) asm volatile("cp.async.wait_group 1;" ::: "memory");
        else                   asm volatile("cp.async.wait_group 0;" ::: "memory");
        __syncthreads();
        int buf = ch & 1;
        uint32_t baseA = sb + SOFF(buf, 0);             // Ahi (Alo = +10240)
        uint32_t baseB = diag ? baseA : sb + SOFF(buf, 2);
#pragma unroll
        for (int kk = 0; kk < 2; kk++) {
            uint32_t ah[2][4], al[2][4];
#pragma unroll
            for (int mt = 0; mt < 2; mt++) {
                uint32_t ad = baseA + (uint32_t)(arow + mt * 16) * 80 + abyt + kk * 32;
                ldsm4(ah[mt], ad);
                ldsm4(al[mt], ad + 10240);
            }
#pragma unroll
            for (int np = 0; np < 4; np++) {
                uint32_t bh[4], bl[4];
                uint32_t bd = baseB + (uint32_t)(brow + np * 16) * 80 + bbyt + kk * 32;
                ldsm4(bh, bd);
                ldsm4(bl, bd + 10240);
#pragma unroll
                for (int mt = 0; mt < 2; mt++) {
#pragma unroll
                    for (int h = 0; h < 2; h++) {
                        float* dacc = acc[mt][np * 2 + h];
                        mma_bf16(dacc, ah[mt], &bh[2 * h]);   // hi*hi
                        mma_bf16(dacc, al[mt], &bh[2 * h]);   // lo*hi
                        mma_bf16(dacc, ah[mt], &bl[2 * h]);   // hi*lo
                    }
                }
            }
        }
        __syncthreads();
        if (ch + 2 < nChunks)
            prefetch_chunk(Zh, Zl, sb, buf, colA, colB, off + (ch + 2) * 32, diag, tid);
    }

    // epilogue: D-frag lane map: c0=D[g][2t], c1=D[g][2t+1], c2=D[g+8][2t], c3=D[g+8][2t+1]
    int g = lane >> 2, t = lane & 3;
#pragma unroll
    for (int mt = 0; mt < 2; mt++) {
#pragma unroll
        for (int nt = 0; nt < 8; nt++) {
            int r = colA + wm * 32 + mt * 16 + g;
            int c = colB + wn * 64 + nt * 8 + 2 * t;
            float* ac = acc[mt][nt];
            *(float2*)&G[(size_t)r * D + c]       = make_float2(ac[0], ac[1]);
            *(float2*)&G[(size_t)(r + 8) * D + c] = make_float2(ac[2], ac[3]);
            if (!diag) {
                G[(size_t)c * D + r]           = ac[0];
                G[(size_t)(c + 1) * D + r]     = ac[1];
                G[(size_t)c * D + r + 8]       = ac[2];
                G[(size_t)(c + 1) * D + r + 8] = ac[3];
            }
        }
    }
}

// ---------------- assemble A_m = I + s_m * (source Gram(s)) ----------------
__global__ __launch_bounds__(256) void assemble_kernel() {
    int m = blockIdx.y;
    int idx = blockIdx.x * 256 + threadIdx.x;
    float s = d_scales[m];
    float v;
    if (m < 2) {
        int t = m * 10;
        float sum = 0.f;
#pragma unroll
        for (int j = 0; j < 10; j++) sum += d_G[t + j][idx];
        v = sum;
    } else if (m < 12) {
        v = d_G[m - 2][idx];
    } else if (m < 22) {
        v = d_G[10 + (m - 12)][idx];
    } else {
        v = d_G[m - 22][idx] + d_G[10 + (m - 22)][idx];
    }
    v *= s;
    int r = idx >> 10, c = idx & 1023;
    if (r == c) v += 1.0f;
    d_A[m][idx] = v;
}

// ---------------- batched blocked Cholesky (NB = 64) ----------------
__global__ __launch_bounds__(256) void chol_diag(int base) {
    __shared__ float s[64][65];
    float* A = d_A[blockIdx.x];
    int tid = threadIdx.x;
    for (int idx = tid; idx < 4096; idx += 256) {
        int r = idx >> 6, c = idx & 63;
        s[r][c] = A[(size_t)(base + r) * D + base + c];
    }
    __syncthreads();
    for (int jc = 0; jc < 64; jc++) {
        if (tid == 0) s[jc][jc] = sqrtf(s[jc][jc]);
        __syncthreads();
        float dinv = 1.0f / s[jc][jc];
        for (int r = jc + 1 + tid; r < 64; r += 256) s[r][jc] *= dinv;
        __syncthreads();
#pragma unroll
        for (int p = 0; p < 16; p++) {
            int idx2 = p * 256 + tid;
            int r = idx2 >> 6, c = idx2 & 63;
            if (r > jc && c > jc) s[r][c] -= s[r][jc] * s[c][jc];
        }
        __syncthreads();
    }
    for (int idx = tid; idx < 4096; idx += 256) {
        int r = idx >> 6, c = idx & 63;
        A[(size_t)(base + r) * D + base + c] = s[r][c];
    }
}

__global__ __launch_bounds__(128) void chol_trsm(int base) {
    __shared__ float L[64][65];
    __shared__ float dinv[64];
    float* A = d_A[blockIdx.x];
    int tid = threadIdx.x;
    for (int idx = tid; idx < 4096; idx += 128) {
        int r = idx >> 6, c = idx & 63;
        L[r][c] = A[(size_t)(base + r) * D + base + c];
    }
    __syncthreads();
    if (tid < 64) dinv[tid] = 1.0f / L[tid][tid];
    __syncthreads();
    int row = base + 64 + blockIdx.y * 128 + tid;
    if (row < D) {
        float* Ap = A + (size_t)row * D + base;
        float x[64];
#pragma unroll
        for (int c = 0; c < 64; c += 4) {
            float4 v = *(const float4*)(Ap + c);
            x[c] = v.x; x[c + 1] = v.y; x[c + 2] = v.z; x[c + 3] = v.w;
        }
#pragma unroll
        for (int i = 0; i < 64; i++) {
            float xi = x[i] * dinv[i];
            x[i] = xi;
#pragma unroll
            for (int jj = i + 1; jj < 64; jj++) x[jj] -= L[jj][i] * xi;
        }
#pragma unroll
        for (int c = 0; c < 64; c += 4) {
            float4 v = make_float4(x[c], x[c + 1], x[c + 2], x[c + 3]);
            *(float4*)(Ap + c) = v;
        }
    }
}

__global__ __launch_bounds__(256) void chol_syrk(int base, int T) {
    __shared__ float P[64][68];
    __shared__ float Q[64][68];
    float* A = d_A[blockIdx.x];
    int p = blockIdx.y;
    int bj = 0;
    while (p >= T - bj) { p -= T - bj; bj++; }
    int bi = bj + p;
    int r0 = base + 64 + bi * 64;
    int c0 = base + 64 + bj * 64;
    int tid = threadIdx.x;
    for (int idx = tid; idx < 4096; idx += 256) {
        int i = idx >> 6, k = idx & 63;
        P[k][i] = A[(size_t)(r0 + i) * D + base + k];
    }
    for (int idx = tid; idx < 4096; idx += 256) {
        int i = idx >> 6, k = idx & 63;
        Q[k][i] = A[(size_t)(c0 + i) * D + base + k];
    }
    __syncthreads();
    int ti = (tid >> 4) * 4, tj = (tid & 15) * 4;
    float acc[4][4];
#pragma unroll
    for (int i = 0; i < 4; i++)
#pragma unroll
        for (int q = 0; q < 4; q++) acc[i][q] = 0.f;
#pragma unroll
    for (int k = 0; k < 64; k++) {
        float4 av = *(const float4*)&P[k][ti];
        float4 bv = *(const float4*)&Q[k][tj];
        acc[0][0] += av.x * bv.x; acc[0][1] += av.x * bv.y; acc[0][2] += av.x * bv.z; acc[0][3] += av.x * bv.w;
        acc[1][0] += av.y * bv.x; acc[1][1] += av.y * bv.y; acc[1][2] += av.y * bv.z; acc[1][3] += av.y * bv.w;
        acc[2][0] += av.z * bv.x; acc[2][1] += av.z * bv.y; acc[2][2] += av.z * bv.z; acc[2][3] += av.z * bv.w;
        acc[3][0] += av.w * bv.x; acc[3][1] += av.w * bv.y; acc[3][2] += av.w * bv.z; acc[3][3] += av.w * bv.w;
    }
#pragma unroll
    for (int i = 0; i < 4; i++) {
        float* dst = A + (size_t)(r0 + ti + i) * D + c0 + tj;
        float4 old = *(const float4*)dst;
        old.x -= acc[i][0]; old.y -= acc[i][1]; old.z -= acc[i][2]; old.w -= acc[i][3];
        *(float4*)dst = old;
    }
}

// ---------------- logdet from Cholesky diagonal + final scalar ----------------
__global__ void logdet_kernel() {
    __shared__ double red[256];
    int m = blockIdx.x;
    int tid = threadIdx.x;
    double s = 0.0;
    for (int i = tid; i < D; i += 256) s += log((double)d_A[m][(size_t)i * D + i]);
    red[tid] = s;
    __syncthreads();
    for (int st = 128; st > 0; st >>= 1) {
        if (tid < st) red[tid] += red[tid + st];
        __syncthreads();
    }
    if (tid == 0) d_logdet[m] = 2.0 * red[0];
}

__global__ void final_kernel(float* out) {
    if (threadIdx.x != 0) return;
    const double n = (double)NROWS;
    double total = 0.0;
    double compZ = 0.0, compH = 0.0;
    for (int j = 0; j < NCLS; j++) {
        double cj = (double)d_counts[j];
        double tr = cj + 1e-8;
        compZ += tr / (2.0 * n) * d_logdet[2 + j];
        compH += tr / (2.0 * n) * d_logdet[12 + j];
    }
    total += -(d_logdet[0] * 0.5 - compZ);
    total += -(d_logdet[1] * 0.5 - compH);
    for (int j = 0; j < NCLS; j++) {
        double cj = (double)d_counts[j];
        double tr = cj + 1e-8;
        total += -(d_logdet[22 + j] * 0.5 - tr / (4.0 * cj) * (d_logdet[2 + j] + d_logdet[12 + j]));
    }
    out[0] = (float)total;
}

// ---------------- launch ----------------
extern "C" void kernel_launch(void* const* d_in, const int* in_sizes, int n_in,
                              void* d_out, int out_size) {
    const float* Z = nullptr;
    const float* Zb = nullptr;
    const int* lab = nullptr;
    int bigSeen = 0;
    for (int i = 0; i < n_in; i++) {
        if (in_sizes[i] == NROWS) {
            lab = (const int*)d_in[i];
        } else {
            if (bigSeen == 0) Z = (const float*)d_in[i];
            else              Zb = (const float*)d_in[i];
            bigSeen++;
        }
    }

    cudaFuncSetAttribute(gram_mma, cudaFuncAttributeMaxDynamicSharedMemorySize, GRAM_SMEM);

    init_permpad<<<(PADN + 255) / 256, 256>>>();
    count_kernel<<<NBLK, 256>>>(lab);
    scan_kernel<<<1, 32>>>();
    scatter_kernel<<<NBLK, 256>>>(lab);
    convert_kernel<<<dim3(PADN / 32, 32, 2), 256>>>(Z, Zb);

    gram_mma<<<dim3(36, 10, 2), 256, GRAM_SMEM>>>();
    assemble_kernel<<<dim3(4096, 32), 256>>>();

    for (int k = 0; k < 16; k++) {
        int base = k * 64;
        chol_diag<<<32, 256>>>(base);
        int rem = D - base - 64;
        if (rem > 0) {
            chol_trsm<<<dim3(32, (rem + 127) / 128), 128>>>(base);
            int T = rem / 64;
            chol_syrk<<<dim3(32, T * (T + 1) / 2), 256>>>(base, T);
        }
    }

    logdet_kernel<<<32, 256>>>();
    final_kernel<<<1, 32>>>((float*)d_out);
}

// round 12
// speedup vs baseline: 1.0004x; 1.0004x over previous
#include <cuda_runtime.h>
#include <cuda_bf16.h>
#include <math.h>
#include <stdint.h>

#define NROWS 32768
#define D 1024
#define NCLS 10
#define NBLK 128           /* NROWS / 256 */
#define PADN 33408         /* 32768 + 10*64 : padded permuted-row capacity */

// ---------------- static device scratch (no runtime allocation) ----------------
__device__ int    d_counts[NCLS];
__device__ int    d_poff[NCLS];        // padded class starts
__device__ int    d_plen[NCLS];        // padded class lengths (mult of 64)
__device__ int    d_blockCnt[NBLK][NCLS];
__device__ int    d_permPad[PADN];     // padded permuted index -> original row (-1 = hole)
__device__ float  d_scales[32];
__device__ float  d_G[20][D * D];      // 0..9: GZ_j, 10..19: GZb_j
__device__ float  d_A[32][D * D];      // matrices to factorize
__device__ double d_logdet[32];
__device__ __nv_bfloat16 d_Zhi[2][(size_t)D * PADN];  // transposed, permuted, padded
__device__ __nv_bfloat16 d_Zlo[2][(size_t)D * PADN];

// ---------------- PTX helpers (base ISA only: ldmatrix / mma.sync / cp.async) ----------------
__device__ __forceinline__ uint32_t smem_u32(const void* p) {
    uint32_t a;
    asm("{ .reg .u64 t; cvta.to.shared.u64 t, %1; cvt.u32.u64 %0, t; }" : "=r"(a) : "l"(p));
    return a;
}
__device__ __forceinline__ void ldsm4(uint32_t* r, uint32_t addr) {
    asm volatile("ldmatrix.sync.aligned.m8n8.x4.shared.b16 {%0,%1,%2,%3}, [%4];"
                 : "=r"(r[0]), "=r"(r[1]), "=r"(r[2]), "=r"(r[3]) : "r"(addr));
}
__device__ __forceinline__ void mma_bf16(float* d, const uint32_t* a, const uint32_t* b) {
    asm volatile(
        "mma.sync.aligned.m16n8k16.row.col.f32.bf16.bf16.f32 "
        "{%0,%1,%2,%3}, {%4,%5,%6,%7}, {%8,%9}, {%0,%1,%2,%3};"
        : "+f"(d[0]), "+f"(d[1]), "+f"(d[2]), "+f"(d[3])
        : "r"(a[0]), "r"(a[1]), "r"(a[2]), "r"(a[3]), "r"(b[0]), "r"(b[1]));
}
__device__ __forceinline__ void cp16(uint32_t dst, const void* src) {
    asm volatile("cp.async.cg.shared.global [%0], [%1], 16;" :: "r"(dst), "l"(src));
}

// ---------------- label histogram / padded stable permutation ----------------
__global__ void init_permpad() {
    int i = blockIdx.x * 256 + threadIdx.x;
    if (i < PADN) d_permPad[i] = -1;
}

__global__ void count_kernel(const int* __restrict__ lab) {
    __shared__ int cnt[NCLS];
    int tid = threadIdx.x;
    if (tid < NCLS) cnt[tid] = 0;
    __syncthreads();
    atomicAdd(&cnt[lab[blockIdx.x * 256 + tid]], 1);
    __syncthreads();
    if (tid < NCLS) d_blockCnt[blockIdx.x][tid] = cnt[tid];
}

__global__ void scan_kernel() {
    if (threadIdx.x != 0) return;
    int poff = 0;
    for (int c = 0; c < NCLS; c++) {
        d_poff[c] = poff;
        int run = poff;
        for (int b = 0; b < NBLK; b++) {
            int v = d_blockCnt[b][c];
            d_blockCnt[b][c] = run;   // padded-domain start for block b, class c
            run += v;
        }
        int cnt = run - poff;
        d_counts[c] = cnt;
        d_plen[c] = (cnt + 63) & ~63;
        poff += d_plen[c];
    }
    d_scales[0] = d_scales[1] = (float)((double)D / ((double)NROWS * 0.5));
    for (int c = 0; c < NCLS; c++) {
        double cj = (double)d_counts[c];
        double tr = cj + 1e-8;
        float s = (float)((double)D / (tr * 0.5));
        d_scales[2 + c]  = s;
        d_scales[12 + c] = s;
        d_scales[22 + c] = (float)((double)D / (2.0 * cj * 0.5));
    }
}

__global__ void scatter_kernel(const int* __restrict__ lab) {
    __shared__ int s_lab[256];
    int tid = threadIdx.x;
    int gid = blockIdx.x * 256 + tid;
    int c = lab[gid];
    s_lab[tid] = c;
    __syncthreads();
    int rank = 0;
    for (int j = 0; j < tid; j++) rank += (s_lab[j] == c);
    d_permPad[d_blockCnt[blockIdx.x][c] + rank] = gid;
}

// ---------------- transpose + fp32 -> bf16(hi,lo) convert ----------------
__global__ __launch_bounds__(256) void convert_kernel(const float* __restrict__ Z0,
                                                      const float* __restrict__ Z1) {
    const float* __restrict__ Z = blockIdx.z ? Z1 : Z0;
    __nv_bfloat16* __restrict__ Th = d_Zhi[blockIdx.z];
    __nv_bfloat16* __restrict__ Tl = d_Zlo[blockIdx.z];
    int i0 = blockIdx.x * 32, m0 = blockIdx.y * 32;
    int tx = threadIdx.x & 31, ty = threadIdx.x >> 5;
    __shared__ float s[32][33];
    __shared__ int rp[32];
    if (threadIdx.x < 32) rp[threadIdx.x] = d_permPad[i0 + threadIdx.x];
    __syncthreads();
#pragma unroll
    for (int q = 0; q < 4; q++) {
        int il = ty + q * 8;
        int r = rp[il];
        s[il][tx] = (r >= 0) ? Z[(size_t)r * D + m0 + tx] : 0.0f;
    }
    __syncthreads();
#pragma unroll
    for (int q = 0; q < 4; q++) {
        int ml = ty + q * 8;
        float x = s[tx][ml];
        __nv_bfloat16 h = __float2bfloat16(x);
        __nv_bfloat16 l = __float2bfloat16(x - __bfloat162float(h));
        size_t o = (size_t)(m0 + ml) * PADN + i0 + tx;
        Th[o] = h;
        Tl[o] = l;
    }
}

// ---------------- per-class Gram via mma.sync bf16-split (3 MMAs) ----------------
// Block: 256 thr (8 warps, 4x2), tile 128x128, K-chunks of 32, cp.async 2-stage.
// smem parts per buffer (stride 80B/row): 0=Ahi 1=Alo 2=Bhi 3=Blo, 10240B each.
#define SOFF(buf, part) ((buf) * 40960 + (part) * 10240)
#define GRAM_SMEM (2 * 40960)

__device__ __forceinline__ void prefetch_chunk(const __nv_bfloat16* __restrict__ Zh,
                                               const __nv_bfloat16* __restrict__ Zl,
                                               uint32_t sb, int buf, int colA, int colB,
                                               int kb, bool diag, int tid) {
    int total = diag ? 1024 : 2048;
    for (int c = tid; c < total; c += 256) {
        int mat = c >> 9;            // 0=Ahi 1=Alo 2=Bhi 3=Blo
        int cc = c & 511;
        int m = cc >> 2, q = cc & 3;
        int col = (mat < 2) ? colA : colB;
        const __nv_bfloat16* base = (mat & 1) ? Zl : Zh;
        const __nv_bfloat16* src = base + (size_t)(col + m) * PADN + kb + q * 8;
        uint32_t dst = sb + SOFF(buf, mat) + m * 80 + q * 16;
        cp16(dst, src);
    }
    asm volatile("cp.async.commit_group;" ::: "memory");
}

__global__ __launch_bounds__(256, 1) void gram_mma() {
    extern __shared__ char smem[];
    uint32_t sb = smem_u32(smem);
    int tid = threadIdx.x;
    int wid = tid >> 5, lane = tid & 31;
    int a = 0, b = blockIdx.x;
    while (b >= 8 - a) { b -= 8 - a; a++; }
    b += a;
    int j = blockIdx.y, z = blockIdx.z;
    bool diag = (a == b);
    float* __restrict__ G = d_G[z * 10 + j];
    const __nv_bfloat16* __restrict__ Zh = d_Zhi[z];
    const __nv_bfloat16* __restrict__ Zl = d_Zlo[z];
    int off = d_poff[j];
    int nChunks = d_plen[j] >> 5;
    int colA = a * 128, colB = b * 128;

    if (nChunks == 0) {   // empty class: zero tile (+ mirror)
        if (tid < 128) {
            float4 z4 = make_float4(0.f, 0.f, 0.f, 0.f);
            for (int c = 0; c < 128; c += 4)
                *(float4*)&G[(size_t)(colA + tid) * D + colB + c] = z4;
            if (!diag)
                for (int c = 0; c < 128; c++)
                    G[(size_t)(colB + c) * D + colA + tid] = 0.f;
        }
        return;
    }

    int wm = wid & 3, wn = wid >> 2;          // warp tile: rows wm*32, cols wn*64
    int sub = lane & 7, idx = lane >> 3;
    int i0 = idx & 1, i1 = idx >> 1;
    // ldmatrix lane-address components
    int arow = wm * 32 + sub + i0 * 8;        // + mt*16
    int abyt = i1 * 16;                       // + kk*32
    int brow = wn * 64 + sub + i1 * 8;        // + np*16
    int bbyt = i0 * 16;                       // + kk*32

    float acc[2][8][4];
#pragma unroll
    for (int mt = 0; mt < 2; mt++)
#pragma unroll
        for (int nt = 0; nt < 8; nt++)
#pragma unroll
            for (int q = 0; q < 4; q++) acc[mt][nt][q] = 0.f;

    prefetch_chunk(Zh, Zl, sb, 0, colA, colB, off, diag, tid);
    if (nChunks > 1)
        prefetch_chunk(Zh, Zl, sb, 1, colA, colB, off + 32, diag, tid);

    for (int ch = 0; ch < nChunks; ch++) {
        if (ch + 2 <= nChunks) asm volatile("cp.async.wait_group 1;" ::: "memory");
        else                   asm volatile("cp.async.wait_group 0;" ::: "memory");
        __syncthreads();
        int buf = ch & 1;
        uint32_t baseA = sb + SOFF(buf, 0);             // Ahi (Alo = +10240)
        uint32_t baseB = diag ? baseA : sb + SOFF(buf, 2);
#pragma unroll
        for (int kk = 0; kk < 2; kk++) {
            uint32_t ah[2][4], al[2][4];
#pragma unroll
            for (int mt = 0; mt < 2; mt++) {
                uint32_t ad = baseA + (uint32_t)(arow + mt * 16) * 80 + abyt + kk * 32;
                ldsm4(ah[mt], ad);
                ldsm4(al[mt], ad + 10240);
            }
#pragma unroll
            for (int np = 0; np < 4; np++) {
                uint32_t bh[4], bl[4];
                uint32_t bd = baseB + (uint32_t)(brow + np * 16) * 80 + bbyt + kk * 32;
                ldsm4(bh, bd);
                ldsm4(bl, bd + 10240);
#pragma unroll
                for (int mt = 0; mt < 2; mt++) {
#pragma unroll
                    for (int h = 0; h < 2; h++) {
                        float* dacc = acc[mt][np * 2 + h];
                        mma_bf16(dacc, ah[mt], &bh[2 * h]);   // hi*hi
                        mma_bf16(dacc, al[mt], &bh[2 * h]);   // lo*hi
                        mma_bf16(dacc, ah[mt], &bl[2 * h]);   // hi*lo
                    }
                }
            }
        }
        __syncthreads();
        if (ch + 2 < nChunks)
            prefetch_chunk(Zh, Zl, sb, buf, colA, colB, off + (ch + 2) * 32, diag, tid);
    }

    // epilogue: D-frag lane map: c0=D[g][2t], c1=D[g][2t+1], c2=D[g+8][2t], c3=D[g+8][2t+1]
    int g = lane >> 2, t = lane & 3;
#pragma unroll
    for (int mt = 0; mt < 2; mt++) {
#pragma unroll
        for (int nt = 0; nt < 8; nt++) {
            int r = colA + wm * 32 + mt * 16 + g;
            int c = colB + wn * 64 + nt * 8 + 2 * t;
            float* ac = acc[mt][nt];
            *(float2*)&G[(size_t)r * D + c]       = make_float2(ac[0], ac[1]);
            *(float2*)&G[(size_t)(r + 8) * D + c] = make_float2(ac[2], ac[3]);
            if (!diag) {
                G[(size_t)c * D + r]           = ac[0];
                G[(size_t)(c + 1) * D + r]     = ac[1];
                G[(size_t)c * D + r + 8]       = ac[2];
                G[(size_t)(c + 1) * D + r + 8] = ac[3];
            }
        }
    }
}

// ---------------- assemble A_m = I + s_m * (source Gram(s)) ----------------
__global__ __launch_bounds__(256) void assemble_kernel() {
    int m = blockIdx.y;
    int idx = blockIdx.x * 256 + threadIdx.x;
    float s = d_scales[m];
    float v;
    if (m < 2) {
        int t = m * 10;
        float sum = 0.f;
#pragma unroll
        for (int j = 0; j < 10; j++) sum += d_G[t + j][idx];
        v = sum;
    } else if (m < 12) {
        v = d_G[m - 2][idx];
    } else if (m < 22) {
        v = d_G[10 + (m - 12)][idx];
    } else {
        v = d_G[m - 22][idx] + d_G[10 + (m - 22)][idx];
    }
    v *= s;
    int r = idx >> 10, c = idx & 1023;
    if (r == c) v += 1.0f;
    d_A[m][idx] = v;
}

// ---------------- batched blocked Cholesky (NB = 64) ----------------
__global__ __launch_bounds__(256) void chol_diag(int base) {
    __shared__ float s[64][65];
    float* A = d_A[blockIdx.x];
    int tid = threadIdx.x;
    for (int idx = tid; idx < 4096; idx += 256) {
        int r = idx >> 6, c = idx & 63;
        s[r][c] = A[(size_t)(base + r) * D + base + c];
    }
    __syncthreads();
    for (int jc = 0; jc < 64; jc++) {
        if (tid == 0) s[jc][jc] = sqrtf(s[jc][jc]);
        __syncthreads();
        float dinv = 1.0f / s[jc][jc];
        for (int r = jc + 1 + tid; r < 64; r += 256) s[r][jc] *= dinv;
        __syncthreads();
#pragma unroll
        for (int p = 0; p < 16; p++) {
            int idx2 = p * 256 + tid;
            int r = idx2 >> 6, c = idx2 & 63;
            if (r > jc && c > jc) s[r][c] -= s[r][jc] * s[c][jc];
        }
        __syncthreads();
    }
    for (int idx = tid; idx < 4096; idx += 256) {
        int r = idx >> 6, c = idx & 63;
        A[(size_t)(base + r) * D + base + c] = s[r][c];
    }
}

__global__ __launch_bounds__(128) void chol_trsm(int base) {
    __shared__ float L[64][65];
    __shared__ float dinv[64];
    float* A = d_A[blockIdx.x];
    int tid = threadIdx.x;
    for (int idx = tid; idx < 4096; idx += 128) {
        int r = idx >> 6, c = idx & 63;
        L[r][c] = A[(size_t)(base + r) * D + base + c];
    }
    __syncthreads();
    if (tid < 64) dinv[tid] = 1.0f / L[tid][tid];
    __syncthreads();
    int row = base + 64 + blockIdx.y * 128 + tid;
    if (row < D) {
        float* Ap = A + (size_t)row * D + base;
        float x[64];
#pragma unroll
        for (int c = 0; c < 64; c += 4) {
            float4 v = *(const float4*)(Ap + c);
            x[c] = v.x; x[c + 1] = v.y; x[c + 2] = v.z; x[c + 3] = v.w;
        }
#pragma unroll
        for (int i = 0; i < 64; i++) {
            float xi = x[i] * dinv[i];
            x[i] = xi;
#pragma unroll
            for (int jj = i + 1; jj < 64; jj++) x[jj] -= L[jj][i] * xi;
        }
#pragma unroll
        for (int c = 0; c < 64; c += 4) {
            float4 v = make_float4(x[c], x[c + 1], x[c + 2], x[c + 3]);
            *(float4*)(Ap + c) = v;
        }
    }
}

__global__ __launch_bounds__(256) void chol_syrk(int base, int T) {
    __shared__ float P[64][68];
    __shared__ float Q[64][68];
    float* A = d_A[blockIdx.x];
    int p = blockIdx.y;
    int bj = 0;
    while (p >= T - bj) { p -= T - bj; bj++; }
    int bi = bj + p;
    int r0 = base + 64 + bi * 64;
    int c0 = base + 64 + bj * 64;
    int tid = threadIdx.x;
    for (int idx = tid; idx < 4096; idx += 256) {
        int i = idx >> 6, k = idx & 63;
        P[k][i] = A[(size_t)(r0 + i) * D + base + k];
    }
    for (int idx = tid; idx < 4096; idx += 256) {
        int i = idx >> 6, k = idx & 63;
        Q[k][i] = A[(size_t)(c0 + i) * D + base + k];
    }
    __syncthreads();
    int ti = (tid >> 4) * 4, tj = (tid & 15) * 4;
    float acc[4][4];
#pragma unroll
    for (int i = 0; i < 4; i++)
#pragma unroll
        for (int q = 0; q < 4; q++) acc[i][q] = 0.f;
#pragma unroll
    for (int k = 0; k < 64; k++) {
        float4 av = *(const float4*)&P[k][ti];
        float4 bv = *(const float4*)&Q[k][tj];
        acc[0][0] += av.x * bv.x; acc[0][1] += av.x * bv.y; acc[0][2] += av.x * bv.z; acc[0][3] += av.x * bv.w;
        acc[1][0] += av.y * bv.x; acc[1][1] += av.y * bv.y; acc[1][2] += av.y * bv.z; acc[1][3] += av.y * bv.w;
        acc[2][0] += av.z * bv.x; acc[2][1] += av.z * bv.y; acc[2][2] += av.z * bv.z; acc[2][3] += av.z * bv.w;
        acc[3][0] += av.w * bv.x; acc[3][1] += av.w * bv.y; acc[3][2] += av.w * bv.z; acc[3][3] += av.w * bv.w;
    }
#pragma unroll
    for (int i = 0; i < 4; i++) {
        float* dst = A + (size_t)(r0 + ti + i) * D + c0 + tj;
        float4 old = *(const float4*)dst;
        old.x -= acc[i][0]; old.y -= acc[i][1]; old.z -= acc[i][2]; old.w -= acc[i][3];
        *(float4*)dst = old;
    }
}

// ---------------- logdet from Cholesky diagonal + final scalar ----------------
__global__ void logdet_kernel() {
    __shared__ double red[256];
    int m = blockIdx.x;
    int tid = threadIdx.x;
    double s = 0.0;
    for (int i = tid; i < D; i += 256) s += log((double)d_A[m][(size_t)i * D + i]);
    red[tid] = s;
    __syncthreads();
    for (int st = 128; st > 0; st >>= 1) {
        if (tid < st) red[tid] += red[tid + st];
        __syncthreads();
    }
    if (tid == 0) d_logdet[m] = 2.0 * red[0];
}

__global__ void final_kernel(float* out) {
    if (threadIdx.x != 0) return;
    const double n = (double)NROWS;
    double total = 0.0;
    double compZ = 0.0, compH = 0.0;
    for (int j = 0; j < NCLS; j++) {
        double cj = (double)d_counts[j];
        double tr = cj + 1e-8;
        compZ += tr / (2.0 * n) * d_logdet[2 + j];
        compH += tr / (2.0 * n) * d_logdet[12 + j];
    }
    total += -(d_logdet[0] * 0.5 - compZ);
    total += -(d_logdet[1] * 0.5 - compH);
    for (int j = 0; j < NCLS; j++) {
        double cj = (double)d_counts[j];
        double tr = cj + 1e-8;
        total += -(d_logdet[22 + j] * 0.5 - tr / (4.0 * cj) * (d_logdet[2 + j] + d_logdet[12 + j]));
    }
    out[0] = (float)total;
}

// ---------------- launch ----------------
extern "C" void kernel_launch(void* const* d_in, const int* in_sizes, int n_in,
                              void* d_out, int out_size) {
    const float* Z = nullptr;
    const float* Zb = nullptr;
    const int* lab = nullptr;
    int bigSeen = 0;
    for (int i = 0; i < n_in; i++) {
        if (in_sizes[i] == NROWS) {
            lab = (const int*)d_in[i];
        } else {
            if (bigSeen == 0) Z = (const float*)d_in[i];
            else              Zb = (const float*)d_in[i];
            bigSeen++;
        }
    }

    cudaFuncSetAttribute(gram_mma, cudaFuncAttributeMaxDynamicSharedMemorySize, GRAM_SMEM);

    init_permpad<<<(PADN + 255) / 256, 256>>>();
    count_kernel<<<NBLK, 256>>>(lab);
    scan_kernel<<<1, 32>>>();
    scatter_kernel<<<NBLK, 256>>>(lab);
    convert_kernel<<<dim3(PADN / 32, 32, 2), 256>>>(Z, Zb);

    gram_mma<<<dim3(36, 10, 2), 256, GRAM_SMEM>>>();
    assemble_kernel<<<dim3(4096, 32), 256>>>();

    for (int k = 0; k < 16; k++) {
        int base = k * 64;
        chol_diag<<<32, 256>>>(base);
        int rem = D - base - 64;
        if (rem > 0) {
            chol_trsm<<<dim3(32, (rem + 127) / 128), 128>>>(base);
            int T = rem / 64;
            chol_syrk<<<dim3(32, T * (T + 1) / 2), 256>>>(base, T);
        }
    }

    logdet_kernel<<<32, 256>>>();
    final_kernel<<<1, 32>>>((float*)d_out);
}